// round 1
// baseline (speedup 1.0000x reference)
#include <cuda_runtime.h>

// Problem constants
#define N_TOK   8192
#define E_EXP   8
#define KSEL    2
#define DIM     2048
#define OUT_ROWS (N_TOK * KSEL)           // 16384
#define TAGS_OFF ((size_t)OUT_ROWS * DIM) // 33554432
#define CNT_OFF  (TAGS_OFF + OUT_ROWS)

// scratch (no allocs allowed)
__device__ int g_tags[OUT_ROWS];

// Pack mask bits into 16-bit fields of two u64 (experts 0-3 in lo, 4-7 in hi)
__device__ __forceinline__ unsigned long long spread4(unsigned int m4) {
    return (unsigned long long)(m4 & 1)
         | ((unsigned long long)((m4 >> 1) & 1) << 16)
         | ((unsigned long long)((m4 >> 2) & 1) << 32)
         | ((unsigned long long)((m4 >> 3) & 1) << 48);
}

// One block, 1024 threads. Each thread handles 8 consecutive tokens:
// top-2 of 8 gates -> mask byte; packed per-expert running counts; block scan;
// then stable scatter of token ids into expert-major order.
__global__ __launch_bounds__(1024) void route_kernel(
    const float* __restrict__ gates, float* __restrict__ out)
{
    __shared__ unsigned long long s_lo[1024];
    __shared__ unsigned long long s_hi[1024];

    const int t = threadIdx.x;
    const int tok0 = t * 8;

    unsigned char mbyte[8];
    unsigned long long lo = 0ull, hi = 0ull;

    #pragma unroll
    for (int i = 0; i < 8; i++) {
        const int n = tok0 + i;
        float g[E_EXP];
        #pragma unroll
        for (int e = 0; e < E_EXP; e++) g[e] = gates[n * E_EXP + e];

        // argmax (first occurrence on tie, matches jax top_k)
        int e1 = 0; float v1 = g[0];
        #pragma unroll
        for (int e = 1; e < E_EXP; e++) if (g[e] > v1) { v1 = g[e]; e1 = e; }
        // second argmax excluding e1
        int e2 = (e1 == 0) ? 1 : 0; float v2 = g[e2];
        #pragma unroll
        for (int e = 0; e < E_EXP; e++) {
            if (e != e1 && g[e] > v2) { v2 = g[e]; e2 = e; }
        }
        unsigned int mb = (1u << e1) | (1u << e2);
        mbyte[i] = (unsigned char)mb;
        lo += spread4(mb & 0xF);
        hi += spread4(mb >> 4);
    }

    s_lo[t] = lo; s_hi[t] = hi;
    __syncthreads();

    // Hillis-Steele inclusive scan over 1024 threads (read/sync/write/sync)
    for (int off = 1; off < 1024; off <<= 1) {
        unsigned long long alo = 0ull, ahi = 0ull;
        if (t >= off) { alo = s_lo[t - off]; ahi = s_hi[t - off]; }
        __syncthreads();
        s_lo[t] += alo; s_hi[t] += ahi;
        __syncthreads();
    }

    const unsigned long long tot_lo = s_lo[1023];
    const unsigned long long tot_hi = s_hi[1023];
    const unsigned long long ex_lo = s_lo[t] - lo;   // exclusive prefix for this thread
    const unsigned long long ex_hi = s_hi[t] - hi;

    int cnt[E_EXP], ebase[E_EXP];
    #pragma unroll
    for (int e = 0; e < 4; e++) {
        cnt[e]     = (int)((tot_lo >> (16 * e)) & 0xFFFF);
        cnt[e + 4] = (int)((tot_hi >> (16 * e)) & 0xFFFF);
    }
    int acc = 0;
    #pragma unroll
    for (int e = 0; e < E_EXP; e++) { ebase[e] = acc; acc += cnt[e]; }

    int run[E_EXP];
    #pragma unroll
    for (int e = 0; e < 4; e++) {
        run[e]     = (int)((ex_lo >> (16 * e)) & 0xFFFF);
        run[e + 4] = (int)((ex_hi >> (16 * e)) & 0xFFFF);
    }

    #pragma unroll
    for (int i = 0; i < 8; i++) {
        const int n = tok0 + i;
        const unsigned int mb = mbyte[i];
        #pragma unroll
        for (int e = 0; e < E_EXP; e++) {
            if ((mb >> e) & 1u) {
                const int dst = ebase[e] + run[e];
                g_tags[dst] = n;
                out[TAGS_OFF + dst] = (float)n;
                run[e]++;
            }
        }
    }

    if (t == 0) {
        #pragma unroll
        for (int e = 0; e < E_EXP; e++) out[CNT_OFF + e] = (float)cnt[e];
    }
}

// One block per output row; 256 threads x 2 float4 = 2048 floats, coalesced.
__global__ __launch_bounds__(256) void gather_kernel(
    const float4* __restrict__ in_flow, float4* __restrict__ out)
{
    const int s = blockIdx.x;
    const int tok = g_tags[s];
    const float4* __restrict__ src = in_flow + (size_t)tok * (DIM / 4);
    float4* __restrict__ dst = out + (size_t)s * (DIM / 4);
    const int i = threadIdx.x;
    dst[i]       = src[i];
    dst[i + 256] = src[i + 256];
}

extern "C" void kernel_launch(void* const* d_in, const int* in_sizes, int n_in,
                              void* d_out, int out_size)
{
    const float* in_flow = (const float*)d_in[0];   // (8192, 2048) f32
    const float* gates   = (const float*)d_in[1];   // (8192, 8)    f32
    float* out = (float*)d_out;

    route_kernel<<<1, 1024>>>(gates, out);
    gather_kernel<<<OUT_ROWS, 256>>>((const float4*)in_flow, (float4*)out);
}

// round 3
// speedup vs baseline: 1.5668x; 1.5668x over previous
#include <cuda_runtime.h>

// Problem constants
#define N_TOK   8192
#define E_EXP   8
#define KSEL    2
#define DIM     2048
#define OUT_ROWS (N_TOK * KSEL)           // 16384
#define TAGS_OFF ((size_t)OUT_ROWS * DIM) // 33554432
#define CNT_OFF  (TAGS_OFF + OUT_ROWS)

// scratch (no allocs allowed)
__device__ int g_tags[OUT_ROWS];
__device__ unsigned char g_mask[N_TOK];

// Pack mask bits into 16-bit fields of two u64 (experts 0-3 in lo, 4-7 in hi)
__device__ __forceinline__ unsigned long long spread4(unsigned int m4) {
    return (unsigned long long)(m4 & 1)
         | ((unsigned long long)((m4 >> 1) & 1) << 16)
         | ((unsigned long long)((m4 >> 2) & 1) << 32)
         | ((unsigned long long)((m4 >> 3) & 1) << 48);
}

// Phase 1: full-chip parallel top-2 mask computation. One thread per token.
// gates row = 32 bytes = 2 x float4 (coalesced-ish vector loads).
__global__ __launch_bounds__(256) void mask_kernel(const float4* __restrict__ gates4)
{
    const int n = blockIdx.x * 256 + threadIdx.x;
    const float4 a = __ldg(gates4 + (size_t)n * 2);
    const float4 b = __ldg(gates4 + (size_t)n * 2 + 1);
    float g[E_EXP] = {a.x, a.y, a.z, a.w, b.x, b.y, b.z, b.w};

    // argmax (first occurrence on tie, matches jax top_k)
    int e1 = 0; float v1 = g[0];
    #pragma unroll
    for (int e = 1; e < E_EXP; e++) if (g[e] > v1) { v1 = g[e]; e1 = e; }
    // second argmax excluding e1
    int e2 = (e1 == 0) ? 1 : 0; float v2 = g[e2];
    #pragma unroll
    for (int e = 0; e < E_EXP; e++) {
        if (e != e1 && g[e] > v2) { v2 = g[e]; e2 = e; }
    }
    g_mask[n] = (unsigned char)((1u << e1) | (1u << e2));
}

// Phase 2: one block, 1024 threads. Each thread loads 8 mask bytes (one u64,
// coalesced), packs per-expert counts, block-wide Hillis-Steele scan, then
// stable scatter of token ids into expert-major order.
__global__ __launch_bounds__(1024) void scan_scatter_kernel(float* __restrict__ out)
{
    __shared__ unsigned long long s_lo[1024];
    __shared__ unsigned long long s_hi[1024];

    const int t = threadIdx.x;
    const int tok0 = t * 8;

    const unsigned long long mword =
        ((const unsigned long long*)g_mask)[t];

    unsigned long long lo = 0ull, hi = 0ull;
    #pragma unroll
    for (int i = 0; i < 8; i++) {
        const unsigned int mb = (unsigned int)((mword >> (8 * i)) & 0xFFu);
        lo += spread4(mb & 0xF);
        hi += spread4(mb >> 4);
    }

    s_lo[t] = lo; s_hi[t] = hi;
    __syncthreads();

    // Hillis-Steele inclusive scan over 1024 threads
    for (int off = 1; off < 1024; off <<= 1) {
        unsigned long long alo = 0ull, ahi = 0ull;
        if (t >= off) { alo = s_lo[t - off]; ahi = s_hi[t - off]; }
        __syncthreads();
        s_lo[t] += alo; s_hi[t] += ahi;
        __syncthreads();
    }

    const unsigned long long tot_lo = s_lo[1023];
    const unsigned long long tot_hi = s_hi[1023];
    const unsigned long long ex_lo = s_lo[t] - lo;   // exclusive prefix
    const unsigned long long ex_hi = s_hi[t] - hi;

    int cnt[E_EXP], ebase[E_EXP];
    #pragma unroll
    for (int e = 0; e < 4; e++) {
        cnt[e]     = (int)((tot_lo >> (16 * e)) & 0xFFFF);
        cnt[e + 4] = (int)((tot_hi >> (16 * e)) & 0xFFFF);
    }
    int acc = 0;
    #pragma unroll
    for (int e = 0; e < E_EXP; e++) { ebase[e] = acc; acc += cnt[e]; }

    int run[E_EXP];
    #pragma unroll
    for (int e = 0; e < 4; e++) {
        run[e]     = (int)((ex_lo >> (16 * e)) & 0xFFFF);
        run[e + 4] = (int)((ex_hi >> (16 * e)) & 0xFFFF);
    }

    #pragma unroll
    for (int i = 0; i < 8; i++) {
        const int n = tok0 + i;
        const unsigned int mb = (unsigned int)((mword >> (8 * i)) & 0xFFu);
        #pragma unroll
        for (int e = 0; e < E_EXP; e++) {
            if ((mb >> e) & 1u) {
                const int dst = ebase[e] + run[e];
                g_tags[dst] = n;
                out[TAGS_OFF + dst] = (float)n;
                run[e]++;
            }
        }
    }

    if (t == 0) {
        #pragma unroll
        for (int e = 0; e < E_EXP; e++) out[CNT_OFF + e] = (float)cnt[e];
    }
}

// One block per output row; 256 threads x 2 float4 = 2048 floats, coalesced.
// Streaming stores (__stcs) keep the 128MB write stream from evicting the
// reusable in_flow rows out of L2.
__global__ __launch_bounds__(256) void gather_kernel(
    const float4* __restrict__ in_flow, float4* __restrict__ out)
{
    const int s = blockIdx.x;
    const int tok = g_tags[s];
    const float4* __restrict__ src = in_flow + (size_t)tok * (DIM / 4);
    float4* __restrict__ dst = out + (size_t)s * (DIM / 4);
    const int i = threadIdx.x;
    const float4 v0 = __ldg(src + i);
    const float4 v1 = __ldg(src + i + 256);
    __stcs(dst + i, v0);
    __stcs(dst + i + 256, v1);
}

extern "C" void kernel_launch(void* const* d_in, const int* in_sizes, int n_in,
                              void* d_out, int out_size)
{
    const float* in_flow = (const float*)d_in[0];   // (8192, 2048) f32
    const float* gates   = (const float*)d_in[1];   // (8192, 8)    f32
    float* out = (float*)d_out;

    mask_kernel<<<N_TOK / 256, 256>>>((const float4*)gates);
    scan_scatter_kernel<<<1, 1024>>>(out);
    gather_kernel<<<OUT_ROWS, 256>>>((const float4*)in_flow, (float4*)out);
}

// round 4
// speedup vs baseline: 1.9036x; 1.2150x over previous
#include <cuda_runtime.h>

#define N_TOK   8192
#define E_EXP   8
#define KSEL    2
#define DIM     2048
#define OUT_ROWS (N_TOK * KSEL)           // 16384
#define TAGS_OFF ((size_t)OUT_ROWS * DIM) // 33554432
#define CNT_OFF  (TAGS_OFF + OUT_ROWS)
#define NBLK    32                        // routing blocks (256 tokens each)

// scratch (no device allocs allowed)
__device__ unsigned char      g_mask[N_TOK];
__device__ unsigned long long g_bcnt_lo[NBLK];
__device__ unsigned long long g_bcnt_hi[NBLK];
__device__ int2               g_dst[N_TOK];

// 4 expert-counters in 16-bit fields of a u64
__device__ __forceinline__ unsigned long long spread4(unsigned int m4) {
    return (unsigned long long)(m4 & 1)
         | ((unsigned long long)((m4 >> 1) & 1) << 16)
         | ((unsigned long long)((m4 >> 2) & 1) << 32)
         | ((unsigned long long)((m4 >> 3) & 1) << 48);
}
__device__ __forceinline__ int fld(unsigned long long v, int e) {
    return (int)((v >> (16 * e)) & 0xFFFF);
}

// ── K1: top-2 mask per token + per-block packed expert counts ──────────────
__global__ __launch_bounds__(256) void mask_cnt_kernel(const float4* __restrict__ gates4)
{
    __shared__ unsigned long long s_lo[8], s_hi[8];
    const int t = threadIdx.x;
    const int n = blockIdx.x * 256 + t;

    const float4 a = __ldg(gates4 + (size_t)n * 2);
    const float4 b = __ldg(gates4 + (size_t)n * 2 + 1);
    float g[E_EXP] = {a.x, a.y, a.z, a.w, b.x, b.y, b.z, b.w};

    int e1 = 0; float v1 = g[0];
    #pragma unroll
    for (int e = 1; e < E_EXP; e++) if (g[e] > v1) { v1 = g[e]; e1 = e; }
    int e2 = (e1 == 0) ? 1 : 0; float v2 = g[e2];
    #pragma unroll
    for (int e = 0; e < E_EXP; e++)
        if (e != e1 && g[e] > v2) { v2 = g[e]; e2 = e; }

    const unsigned int mb = (1u << e1) | (1u << e2);
    g_mask[n] = (unsigned char)mb;

    unsigned long long lo = spread4(mb & 0xF);
    unsigned long long hi = spread4(mb >> 4);
    #pragma unroll
    for (int off = 16; off > 0; off >>= 1) {
        lo += __shfl_down_sync(0xFFFFFFFFu, lo, off);
        hi += __shfl_down_sync(0xFFFFFFFFu, hi, off);
    }
    const int w = t >> 5;
    if ((t & 31) == 0) { s_lo[w] = lo; s_hi[w] = hi; }
    __syncthreads();
    if (t == 0) {
        unsigned long long tl = 0ull, th = 0ull;
        #pragma unroll
        for (int i = 0; i < 8; i++) { tl += s_lo[i]; th += s_hi[i]; }
        g_bcnt_lo[blockIdx.x] = tl;
        g_bcnt_hi[blockIdx.x] = th;
    }
}

// ── K2: per-token destinations (coalesced int2), counts to out ─────────────
__global__ __launch_bounds__(256) void dst_kernel(float* __restrict__ out)
{
    __shared__ unsigned long long sw_lo[8], sw_hi[8];
    const int b = blockIdx.x;
    const int t = threadIdx.x;
    const int n = b * 256 + t;
    const int lane = t & 31, w = t >> 5;

    const unsigned int mb = g_mask[n];
    const unsigned long long lo = spread4(mb & 0xF);
    const unsigned long long hi = spread4(mb >> 4);

    // warp inclusive scan
    unsigned long long slo = lo, shi = hi;
    #pragma unroll
    for (int off = 1; off < 32; off <<= 1) {
        unsigned long long al = __shfl_up_sync(0xFFFFFFFFu, slo, off);
        unsigned long long ah = __shfl_up_sync(0xFFFFFFFFu, shi, off);
        if (lane >= off) { slo += al; shi += ah; }
    }
    if (lane == 31) { sw_lo[w] = slo; sw_hi[w] = shi; }
    __syncthreads();

    unsigned long long plo = 0ull, phi = 0ull;   // warps before mine
    #pragma unroll
    for (int i = 0; i < 8; i++) if (i < w) { plo += sw_lo[i]; phi += sw_hi[i]; }
    const unsigned long long ex_lo = plo + slo - lo;  // exclusive in-block prefix
    const unsigned long long ex_hi = phi + shi - hi;

    // global: totals + prefix over earlier blocks (512B broadcast reads)
    unsigned long long blo = 0ull, bhi = 0ull, tlo = 0ull, thi = 0ull;
    #pragma unroll
    for (int bb = 0; bb < NBLK; bb++) {
        const unsigned long long l = g_bcnt_lo[bb];
        const unsigned long long h = g_bcnt_hi[bb];
        if (bb < b) { blo += l; bhi += h; }
        tlo += l; thi += h;
    }

    int cnt[E_EXP], ebase[E_EXP];
    #pragma unroll
    for (int e = 0; e < 4; e++) { cnt[e] = fld(tlo, e); cnt[e + 4] = fld(thi, e); }
    int acc = 0;
    #pragma unroll
    for (int e = 0; e < E_EXP; e++) { ebase[e] = acc; acc += cnt[e]; }

    int dsts[2]; int k = 0;
    #pragma unroll
    for (int e = 0; e < E_EXP; e++) {
        if ((mb >> e) & 1u) {
            const int pre  = (e < 4) ? fld(blo, e) : fld(bhi, e - 4);
            const int loc  = (e < 4) ? fld(ex_lo, e) : fld(ex_hi, e - 4);
            dsts[k & 1] = ebase[e] + pre + loc;
            k++;
        }
    }
    g_dst[n] = make_int2(dsts[0], dsts[1]);

    if (b == 0 && t == 0) {
        #pragma unroll
        for (int e = 0; e < E_EXP; e++) out[CNT_OFF + e] = (float)cnt[e];
    }
}

// ── K3: token-major gather — read each row ONCE, write to both dsts ────────
__global__ __launch_bounds__(256) void gather_kernel(
    const float4* __restrict__ in_flow, float4* __restrict__ out,
    float* __restrict__ outf)
{
    const int n = blockIdx.x;
    const int2 d = g_dst[n];
    const int t = threadIdx.x;

    const float4* __restrict__ src = in_flow + (size_t)n * (DIM / 4);
    const float4 v0 = __ldg(src + t);
    const float4 v1 = __ldg(src + t + 256);

    float4* __restrict__ dst0 = out + (size_t)d.x * (DIM / 4);
    float4* __restrict__ dst1 = out + (size_t)d.y * (DIM / 4);
    __stcs(dst0 + t,       v0);
    __stcs(dst0 + t + 256, v1);
    __stcs(dst1 + t,       v0);
    __stcs(dst1 + t + 256, v1);

    if (t == 0) {
        outf[TAGS_OFF + d.x] = (float)n;
        outf[TAGS_OFF + d.y] = (float)n;
    }
}

extern "C" void kernel_launch(void* const* d_in, const int* in_sizes, int n_in,
                              void* d_out, int out_size)
{
    const float* in_flow = (const float*)d_in[0];   // (8192, 2048) f32
    const float* gates   = (const float*)d_in[1];   // (8192, 8)    f32
    float* out = (float*)d_out;

    mask_cnt_kernel<<<NBLK, 256>>>((const float4*)gates);
    dst_kernel<<<NBLK, 256>>>(out);
    gather_kernel<<<N_TOK, 256>>>((const float4*)in_flow, (float4*)out, out);
}

// round 5
// speedup vs baseline: 2.1067x; 1.1067x over previous
#include <cuda_runtime.h>

#define N_TOK   8192
#define E_EXP   8
#define KSEL    2
#define DIM     2048
#define OUT_ROWS (N_TOK * KSEL)           // 16384
#define TAGS_OFF ((size_t)OUT_ROWS * DIM) // 33554432
#define CNT_OFF  (TAGS_OFF + OUT_ROWS)
#define NBLK    32                        // routing blocks (256 tokens each)

// scratch (no device allocs allowed)
__device__ unsigned long long g_bcnt_lo[NBLK];
__device__ unsigned long long g_bcnt_hi[NBLK];
__device__ int2               g_dst[N_TOK];
__device__ unsigned int       g_sync;     // monotonic ticket barrier (replay-safe)

// 4 expert-counters in 16-bit fields of a u64
__device__ __forceinline__ unsigned long long spread4(unsigned int m4) {
    return (unsigned long long)(m4 & 1)
         | ((unsigned long long)((m4 >> 1) & 1) << 16)
         | ((unsigned long long)((m4 >> 2) & 1) << 32)
         | ((unsigned long long)((m4 >> 3) & 1) << 48);
}
__device__ __forceinline__ int fld(unsigned long long v, int e) {
    return (int)((v >> (16 * e)) & 0xFFFF);
}

// ── K1: fused routing. 32 blocks; mask stays in registers across a
//    device-wide ticket barrier; only 32x16B block counts cross blocks. ──────
__global__ __launch_bounds__(256) void route_kernel(
    const float4* __restrict__ gates4, float* __restrict__ out)
{
    __shared__ unsigned long long sw_lo[8], sw_hi[8];
    __shared__ unsigned long long sr_lo[8], sr_hi[8];

    const int b = blockIdx.x;
    const int t = threadIdx.x;
    const int n = b * 256 + t;
    const int lane = t & 31, w = t >> 5;

    // ---- top-2 mask (registers only) ----
    const float4 a = __ldg(gates4 + (size_t)n * 2);
    const float4 bb4 = __ldg(gates4 + (size_t)n * 2 + 1);
    float g[E_EXP] = {a.x, a.y, a.z, a.w, bb4.x, bb4.y, bb4.z, bb4.w};

    int e1 = 0; float v1 = g[0];
    #pragma unroll
    for (int e = 1; e < E_EXP; e++) if (g[e] > v1) { v1 = g[e]; e1 = e; }
    int e2 = (e1 == 0) ? 1 : 0; float v2 = g[e2];
    #pragma unroll
    for (int e = 0; e < E_EXP; e++)
        if (e != e1 && g[e] > v2) { v2 = g[e]; e2 = e; }
    const unsigned int mb = (1u << e1) | (1u << e2);

    const unsigned long long lo = spread4(mb & 0xF);
    const unsigned long long hi = spread4(mb >> 4);

    // ---- warp inclusive scan (gives both scan and warp totals) ----
    unsigned long long slo = lo, shi = hi;
    #pragma unroll
    for (int off = 1; off < 32; off <<= 1) {
        unsigned long long al = __shfl_up_sync(0xFFFFFFFFu, slo, off);
        unsigned long long ah = __shfl_up_sync(0xFFFFFFFFu, shi, off);
        if (lane >= off) { slo += al; shi += ah; }
    }
    if (lane == 31) { sw_lo[w] = slo; sw_hi[w] = shi; }
    __syncthreads();

    // block total -> g_bcnt
    if (t == 0) {
        unsigned long long tl = 0ull, th = 0ull;
        #pragma unroll
        for (int i = 0; i < 8; i++) { tl += sw_lo[i]; th += sw_hi[i]; }
        g_bcnt_lo[b] = tl;
        g_bcnt_hi[b] = th;
    }

    // ---- device-wide barrier (monotonic ticket; safe across graph replays) ----
    __syncthreads();
    if (t == 0) {
        __threadfence();
        const unsigned int ticket = atomicAdd(&g_sync, 1u);
        const unsigned int target = (ticket / NBLK + 1u) * NBLK;
        while (atomicAdd(&g_sync, 0u) < target) { }
        __threadfence();
    }
    __syncthreads();

    // ---- global totals + prefix over earlier blocks (512B broadcast) ----
    unsigned long long blo = 0ull, bhi = 0ull, tlo = 0ull, thi = 0ull;
    #pragma unroll
    for (int i = 0; i < NBLK; i++) {
        const unsigned long long l = g_bcnt_lo[i];
        const unsigned long long h = g_bcnt_hi[i];
        if (i < b) { blo += l; bhi += h; }
        tlo += l; thi += h;
    }

    int cnt[E_EXP], ebase[E_EXP];
    #pragma unroll
    for (int e = 0; e < 4; e++) { cnt[e] = fld(tlo, e); cnt[e + 4] = fld(thi, e); }
    int acc = 0;
    #pragma unroll
    for (int e = 0; e < E_EXP; e++) { ebase[e] = acc; acc += cnt[e]; }

    // in-block exclusive prefix for this thread
    unsigned long long plo = 0ull, phi = 0ull;
    #pragma unroll
    for (int i = 0; i < 8; i++) if (i < w) { plo += sw_lo[i]; phi += sw_hi[i]; }
    const unsigned long long ex_lo = plo + slo - lo;
    const unsigned long long ex_hi = phi + shi - hi;

    int dsts[2]; int k = 0;
    #pragma unroll
    for (int e = 0; e < E_EXP; e++) {
        if ((mb >> e) & 1u) {
            const int pre = (e < 4) ? fld(blo, e) : fld(bhi, e - 4);
            const int loc = (e < 4) ? fld(ex_lo, e) : fld(ex_hi, e - 4);
            dsts[k & 1] = ebase[e] + pre + loc;
            k++;
        }
    }
    g_dst[n] = make_int2(dsts[0], dsts[1]);

    if (b == 0 && t == 0) {
        #pragma unroll
        for (int e = 0; e < E_EXP; e++) out[CNT_OFF + e] = (float)cnt[e];
    }
}

// ── K2: token-major gather — read each row ONCE, write to both dsts ────────
__global__ __launch_bounds__(256) void gather_kernel(
    const float4* __restrict__ in_flow, float4* __restrict__ out,
    float* __restrict__ outf)
{
    const int n = blockIdx.x;
    const int2 d = g_dst[n];
    const int t = threadIdx.x;

    const float4* __restrict__ src = in_flow + (size_t)n * (DIM / 4);
    const float4 v0 = __ldg(src + t);
    const float4 v1 = __ldg(src + t + 256);

    float4* __restrict__ dst0 = out + (size_t)d.x * (DIM / 4);
    float4* __restrict__ dst1 = out + (size_t)d.y * (DIM / 4);
    __stcs(dst0 + t,       v0);
    __stcs(dst0 + t + 256, v1);
    __stcs(dst1 + t,       v0);
    __stcs(dst1 + t + 256, v1);

    if (t == 0) {
        outf[TAGS_OFF + d.x] = (float)n;
        outf[TAGS_OFF + d.y] = (float)n;
    }
}

extern "C" void kernel_launch(void* const* d_in, const int* in_sizes, int n_in,
                              void* d_out, int out_size)
{
    const float* in_flow = (const float*)d_in[0];   // (8192, 2048) f32
    const float* gates   = (const float*)d_in[1];   // (8192, 8)    f32
    float* out = (float*)d_out;

    route_kernel<<<NBLK, 256>>>((const float4*)gates, out);
    gather_kernel<<<N_TOK, 256>>>((const float4*)in_flow, (float4*)out, out);
}